// round 9
// baseline (speedup 1.0000x reference)
#include <cuda_runtime.h>
#include <cuda_bf16.h>
#include <cstdint>
#include <math.h>

// ---------------------------------------------------------------------------
// Problem sizes
// ---------------------------------------------------------------------------
#define NB   32
#define C    256
#define HWD  56
#define SP   (HWD*HWD)          // 3136
#define NSP  (NB*SP)            // 100352
#define TOT  ((size_t)NB*C*SP)  // 25,690,112
#define KTOT (C*9)              // 2304

// conv tiling
#define BM 128
#define BN 128
#define NSTEP 36                // 9 taps * 4 ci-chunks of 64
#define STAGES 4
#define A_SM 10240              // 128 rows * 80B (64B data + pad)
#define B_SM 10240
#define STAGE_BYTES (A_SM + B_SM)           // 20480
#define SMEM_TOTAL (STAGES*STAGE_BYTES)     // 81920

#define DINL __device__ __forceinline__

// ---------------------------------------------------------------------------
// Device scratch (allocation-free rule: __device__ globals)
// ---------------------------------------------------------------------------
__device__ int8_t g_ba[(size_t)NB*SP*C];        // binarized acts, NHWC s8 (25.7 MB)
__device__ int8_t g_wq[9*256*256];              // sign(bw), [tap][co][ci]
__device__ float  g_sw[256];                    // per-channel power-of-2 scale
__device__ float  g_y [TOT];                    // conv integer result z (as f32), NCHW
__device__ float  g_psum[256*8];
__device__ float  g_psq [256*8];
__device__ float  g_scale[256];
__device__ float  g_bias [256];

// ---------------------------------------------------------------------------
// PTX helpers (arch-portable only: cp.async / ldmatrix / mma.sync)
// ---------------------------------------------------------------------------
DINL uint32_t smem_u32(const void* p){
    uint32_t a;
    asm("{ .reg .u64 t; cvta.to.shared.u64 t, %1; cvt.u32.u64 %0, t; }" : "=r"(a) : "l"(p));
    return a;
}

DINL void cp16(uint32_t dst, const void* src, bool pred){
    int sz = pred ? 16 : 0;
    asm volatile("cp.async.cg.shared.global [%0], [%1], 16, %2;\n"
                 :: "r"(dst), "l"(src), "r"(sz) : "memory");
}
#define CP_COMMIT() asm volatile("cp.async.commit_group;\n" ::: "memory")
#define CP_WAIT2()  asm volatile("cp.async.wait_group 2;\n" ::: "memory")

DINL void ldmx4(uint32_t* r, uint32_t addr){
    asm volatile("ldmatrix.sync.aligned.m8n8.x4.shared.b16 {%0,%1,%2,%3}, [%4];"
                 : "=r"(r[0]), "=r"(r[1]), "=r"(r[2]), "=r"(r[3]) : "r"(addr));
}

DINL void mma_s8(int* c, const uint32_t* a, uint32_t b0, uint32_t b1){
    asm volatile(
        "mma.sync.aligned.m16n8k32.row.col.s32.s8.s8.s32 "
        "{%0,%1,%2,%3}, {%4,%5,%6,%7}, {%8,%9}, {%0,%1,%2,%3};"
        : "+r"(c[0]), "+r"(c[1]), "+r"(c[2]), "+r"(c[3])
        : "r"(a[0]), "r"(a[1]), "r"(a[2]), "r"(a[3]), "r"(b0), "r"(b1));
}

// ---------------------------------------------------------------------------
// Kernel 1: weight prep.  Per co: mean, unbiased std, sw = 2^round(log2(mean|bw|)),
// store sign(bw) as s8 in [tap][co][ci] layout, sw separately.
// ---------------------------------------------------------------------------
__global__ void __launch_bounds__(256) kwprep(const float* __restrict__ w){
    int co = blockIdx.x;
    int t  = threadIdx.x;
    const float* wr = w + (size_t)co * KTOT;
    __shared__ float red[256];

    float v[9];
    #pragma unroll
    for (int j = 0; j < 9; j++) v[j] = wr[t + j*256];

    float s = 0.f;
    #pragma unroll
    for (int j = 0; j < 9; j++) s += v[j];
    red[t] = s; __syncthreads();
    for (int off = 128; off > 0; off >>= 1){ if (t < off) red[t] += red[t+off]; __syncthreads(); }
    float mean = red[0] / 2304.0f;
    __syncthreads();

    float ss = 0.f, sa = 0.f;
    #pragma unroll
    for (int j = 0; j < 9; j++){ float d = v[j] - mean; ss += d*d; sa += fabsf(d); }
    red[t] = ss; __syncthreads();
    for (int off = 128; off > 0; off >>= 1){ if (t < off) red[t] += red[t+off]; __syncthreads(); }
    float stdv = sqrtf(red[0] / 2303.0f);   // ddof=1
    __syncthreads();
    red[t] = sa; __syncthreads();
    for (int off = 128; off > 0; off >>= 1){ if (t < off) red[t] += red[t+off]; __syncthreads(); }
    float meanabs = red[0] / (stdv * 2304.0f);      // mean|bw|
    float sw = exp2f(rintf(log2f(meanabs)));        // round-half-even, matches jnp.round
    if (t == 0) g_sw[co] = sw;

    #pragma unroll
    for (int j = 0; j < 9; j++){
        int idx = t + j*256;                // = ci*9 + tap  (OIHW inner layout)
        int ci = idx / 9, tap = idx % 9;
        float d = v[j] - mean;
        int8_t b = (d > 0.f) ? 1 : ((d < 0.f) ? -1 : 0);   // sign(0)=0 per jnp.sign
        g_wq[(size_t)tap*65536 + (size_t)co*256 + ci] = b;
    }
}

// ---------------------------------------------------------------------------
// Kernel 2: binarize activations, NCHW fp32 -> NHWC s8 (SMEM transpose)
// ---------------------------------------------------------------------------
__global__ void __launch_bounds__(256) kbin(const float* __restrict__ x){
    __shared__ __align__(16) int8_t sm[HWD][272];
    int h = blockIdx.x, n = blockIdx.y;
    int t = threadIdx.x, wid = t >> 5, lane = t & 31;

    for (int ci = wid; ci < C; ci += 8){
        for (int w = lane; w < HWD; w += 32){
            float v = x[(((size_t)n*C + ci)*HWD + h)*HWD + w];
            sm[w][ci] = (v > 0.f) ? 1 : ((v < 0.f) ? -1 : 0);
        }
    }
    __syncthreads();
    for (int w = wid; w < HWD; w += 8){
        uint2 val = *reinterpret_cast<const uint2*>(&sm[w][lane*8]);
        *reinterpret_cast<uint2*>(&g_ba[(((size_t)(n*HWD + h)*HWD + w) << 8) + lane*8]) = val;
    }
}

// ---------------------------------------------------------------------------
// Kernel 3: conv as 9-tap accumulated int8 mma.sync GEMM
//   CTA: 128 spatial (M) x 128 co (N); K = 2304 in 36 chunks of 64.
//   8 warps in 4(M) x 2(N); warp tile 32x64.
// ---------------------------------------------------------------------------
DINL void load_stage(int k2, int s, uint32_t sb, int t, int n, int ph, int pw,
                     bool prow, int coBase){
    int tap = k2 >> 2, kc = k2 & 3;
    int h2 = ph + tap/3 - 1;
    int w2 = pw + tap%3 - 1;
    bool valid = prow && ((unsigned)h2 < (unsigned)HWD) && ((unsigned)w2 < (unsigned)HWD);
    int r = t >> 1, half = t & 1;

    size_t aoff = valid ? ((((size_t)n*HWD + h2)*HWD + w2)*256 + kc*64) : 0;
    const char* asrc = (const char*)g_ba + aoff + half*32;
    uint32_t abase = sb + s*STAGE_BYTES + r*80 + half*32;
    cp16(abase,      asrc,      valid);
    cp16(abase + 16, asrc + 16, valid);

    const char* bsrc = (const char*)g_wq + (size_t)tap*65536
                     + (size_t)(coBase + r)*256 + kc*64 + half*32;
    uint32_t bbase = sb + s*STAGE_BYTES + A_SM + r*80 + half*32;
    cp16(bbase,      bsrc,      true);
    cp16(bbase + 16, bsrc + 16, true);
    CP_COMMIT();
}

__global__ void __launch_bounds__(256, 2) kconv(){
    extern __shared__ __align__(128) char smem[];
    uint32_t sb = smem_u32(smem);
    int t = threadIdx.x, lane = t & 31, wid = t >> 5;
    int n      = blockIdx.z;
    int coBase = blockIdx.y * BN;
    int p0     = blockIdx.x * BM;
    int wm = wid & 3, wn = wid >> 2;

    // geometry for this thread's load row
    int r  = t >> 1;
    int p  = p0 + r;
    int ph = p / HWD, pw = p % HWD;
    bool prow = p < SP;

    // ldmatrix per-lane address components (verified s8 fragment mappings)
    int arow  = (lane & 7) + ((lane >> 3) & 1) * 8;
    int akoff = (lane >> 4) * 16;
    int brow  = (lane & 7) + (lane >> 4) * 8;
    int bkoff = ((lane >> 3) & 1) * 16;

    int acc[2][8][4];
    #pragma unroll
    for (int mf = 0; mf < 2; mf++)
        #pragma unroll
        for (int nf = 0; nf < 8; nf++)
            #pragma unroll
            for (int q = 0; q < 4; q++) acc[mf][nf][q] = 0;

    // prologue: stages 0..2
    load_stage(0, 0, sb, t, n, ph, pw, prow, coBase);
    load_stage(1, 1, sb, t, n, ph, pw, prow, coBase);
    load_stage(2, 2, sb, t, n, ph, pw, prow, coBase);

    for (int k = 0; k < NSTEP; k++){
        int s = k & 3;
        CP_WAIT2();                 // stage k resident
        __syncthreads();            // also: all warps done with stage (k-1)
        if (k + 3 < NSTEP) load_stage(k + 3, (k + 3) & 3, sb, t, n, ph, pw, prow, coBase);
        else               CP_COMMIT();   // keep group counts uniform

        uint32_t sAb = sb + s*STAGE_BYTES;
        uint32_t sBb = sAb + A_SM;
        #pragma unroll
        for (int ks = 0; ks < 2; ks++){
            uint32_t a[2][4], b[4][4];
            #pragma unroll
            for (int mf = 0; mf < 2; mf++)
                ldmx4(a[mf], sAb + (uint32_t)(wm*32 + mf*16 + arow)*80 + ks*32 + akoff);
            #pragma unroll
            for (int nf2 = 0; nf2 < 4; nf2++)
                ldmx4(b[nf2], sBb + (uint32_t)(wn*64 + nf2*16 + brow)*80 + ks*32 + bkoff);
            #pragma unroll
            for (int mf = 0; mf < 2; mf++)
                #pragma unroll
                for (int nf = 0; nf < 8; nf++)
                    mma_s8(acc[mf][nf], a[mf],
                           b[nf >> 1][(nf & 1)*2], b[nf >> 1][(nf & 1)*2 + 1]);
        }
    }

    // epilogue: s32 -> f32 (exact), NCHW stores in 32B runs
    int g = lane >> 2, tig = lane & 3;
    float* ybase = g_y + (size_t)n * C * SP;
    #pragma unroll
    for (int mf = 0; mf < 2; mf++){
        #pragma unroll
        for (int nf = 0; nf < 8; nf++){
            int co = coBase + wn*64 + nf*8 + tig*2;
            int pp = p0 + wm*32 + mf*16 + g;
            if (pp < SP){
                ybase[(size_t)co     * SP + pp] = __int2float_rn(acc[mf][nf][0]);
                ybase[(size_t)(co+1) * SP + pp] = __int2float_rn(acc[mf][nf][1]);
            }
            if (pp + 8 < SP){
                ybase[(size_t)co     * SP + pp + 8] = __int2float_rn(acc[mf][nf][2]);
                ybase[(size_t)(co+1) * SP + pp + 8] = __int2float_rn(acc[mf][nf][3]);
            }
        }
    }
}

// ---------------------------------------------------------------------------
// Kernel 4: deterministic per-channel partial sums over z  (grid: 8 x 256)
// ---------------------------------------------------------------------------
__global__ void __launch_bounds__(256) kstats(){
    int cx = blockIdx.x;      // 0..7 -> 4 images each
    int co = blockIdx.y;
    int t = threadIdx.x;
    float s = 0.f, q = 0.f;
    for (int nn = cx*4; nn < cx*4 + 4; nn++){
        const float* pl = g_y + ((size_t)nn * C + co) * SP;
        for (int i = t; i < SP; i += 256){ float v = pl[i]; s += v; q += v*v; }
    }
    __shared__ float rs[256], rq[256];
    rs[t] = s; rq[t] = q; __syncthreads();
    for (int off = 128; off > 0; off >>= 1){
        if (t < off){ rs[t] += rs[t+off]; rq[t] += rq[t+off]; }
        __syncthreads();
    }
    if (t == 0){ g_psum[co*8 + cx] = rs[0]; g_psq[co*8 + cx] = rq[0]; }
}

// ---------------------------------------------------------------------------
// Kernel 5: finalize BN scale/bias, folding sw exactly (y = sw*z)
// ---------------------------------------------------------------------------
__global__ void kbnp(const float* __restrict__ gamma, const float* __restrict__ beta){
    int co = threadIdx.x;
    float s = 0.f, q = 0.f;
    #pragma unroll
    for (int i = 0; i < 8; i++){ s += g_psum[co*8 + i]; q += g_psq[co*8 + i]; }
    float sw = g_sw[co];
    float mean_z = s / (float)NSP;
    float var_z  = q / (float)NSP - mean_z*mean_z;        // biased (ddof=0)
    float var_y  = sw*sw*var_z;
    float sc = gamma[co] * rsqrtf(var_y + 1e-5f);
    g_scale[co] = sw * sc;                                // applied to z
    g_bias[co]  = beta[co] - sw * mean_z * sc;
}

// ---------------------------------------------------------------------------
// Kernel 6: apply BN + hardtanh, vectorized float4
// ---------------------------------------------------------------------------
__global__ void __launch_bounds__(256) kapply(float* __restrict__ out){
    size_t i4 = (size_t)blockIdx.x * 256 + threadIdx.x;   // TOT/4 = 6,422,528 exact
    int co = (int)((i4 / (SP/4)) & 255);
    float sc = g_scale[co], b = g_bias[co];
    float4 v = reinterpret_cast<const float4*>(g_y)[i4];
    float4 r;
    r.x = fminf(fmaxf(v.x*sc + b, -1.f), 1.f);
    r.y = fminf(fmaxf(v.y*sc + b, -1.f), 1.f);
    r.z = fminf(fmaxf(v.z*sc + b, -1.f), 1.f);
    r.w = fminf(fmaxf(v.w*sc + b, -1.f), 1.f);
    reinterpret_cast<float4*>(out)[i4] = r;
}

// ---------------------------------------------------------------------------
extern "C" void kernel_launch(void* const* d_in, const int* in_sizes, int n_in,
                              void* d_out, int out_size){
    const float* x     = (const float*)d_in[0];
    const float* w     = (const float*)d_in[1];
    const float* gamma = (const float*)d_in[2];
    const float* beta  = (const float*)d_in[3];
    float* out = (float*)d_out;

    cudaFuncSetAttribute(kconv, cudaFuncAttributeMaxDynamicSharedMemorySize, SMEM_TOTAL);

    kwprep<<<256, 256>>>(w);
    kbin  <<<dim3(HWD, NB), 256>>>(x);
    kconv <<<dim3((SP + BM - 1)/BM, C/BN, NB), 256, SMEM_TOTAL>>>();
    kstats<<<dim3(8, 256), 256>>>();
    kbnp  <<<1, 256>>>(gamma, beta);
    kapply<<<(unsigned)(TOT/4/256), 256>>>(out);
}

// round 10
// speedup vs baseline: 1.0160x; 1.0160x over previous
#include <cuda_runtime.h>
#include <cuda_bf16.h>
#include <cstdint>
#include <math.h>

// ---------------------------------------------------------------------------
// Problem sizes
// ---------------------------------------------------------------------------
#define NB   32
#define C    256
#define HWD  56
#define SP   (HWD*HWD)          // 3136
#define NSP  (NB*SP)            // 100352
#define TOT  ((size_t)NB*C*SP)  // 25,690,112
#define KTOT (C*9)              // 2304

// conv tiling
#define BM 128
#define BN 64
#define NSTEP 36                // 9 taps * 4 ci-chunks of 64
#define STAGES 4
#define A_SM 10240              // 128 rows * 80B (64B data + pad)
#define B_SM 5120               // 64 rows * 80B
#define STAGE_BYTES (A_SM + B_SM)           // 15360
#define SMEM_TOTAL (STAGES*STAGE_BYTES)     // 61440

#define DINL __device__ __forceinline__

// ---------------------------------------------------------------------------
// Device scratch (allocation-free rule: __device__ globals)
// ---------------------------------------------------------------------------
__device__ int8_t g_ba[(size_t)NB*SP*C];        // binarized acts, NHWC s8 (25.7 MB)
__device__ int8_t g_wq[9*256*256];              // sign(bw), [tap][co][ci]
__device__ float  g_sw[256];                    // per-channel power-of-2 scale
__device__ float  g_y [TOT];                    // conv integer result z (as f32), NCHW
__device__ float  g_psum[256*8];
__device__ float  g_psq [256*8];
__device__ float  g_scale[256];
__device__ float  g_bias [256];

// ---------------------------------------------------------------------------
// PTX helpers (arch-portable only: cp.async / ldmatrix / mma.sync)
// ---------------------------------------------------------------------------
DINL uint32_t smem_u32(const void* p){
    uint32_t a;
    asm("{ .reg .u64 t; cvta.to.shared.u64 t, %1; cvt.u32.u64 %0, t; }" : "=r"(a) : "l"(p));
    return a;
}

DINL void cp16(uint32_t dst, const void* src, bool pred){
    int sz = pred ? 16 : 0;
    asm volatile("cp.async.cg.shared.global [%0], [%1], 16, %2;\n"
                 :: "r"(dst), "l"(src), "r"(sz) : "memory");
}
#define CP_COMMIT() asm volatile("cp.async.commit_group;\n" ::: "memory")
#define CP_WAIT2()  asm volatile("cp.async.wait_group 2;\n" ::: "memory")

DINL void ldmx4(uint32_t* r, uint32_t addr){
    asm volatile("ldmatrix.sync.aligned.m8n8.x4.shared.b16 {%0,%1,%2,%3}, [%4];"
                 : "=r"(r[0]), "=r"(r[1]), "=r"(r[2]), "=r"(r[3]) : "r"(addr));
}

DINL void mma_s8(int* c, const uint32_t* a, uint32_t b0, uint32_t b1){
    asm volatile(
        "mma.sync.aligned.m16n8k32.row.col.s32.s8.s8.s32 "
        "{%0,%1,%2,%3}, {%4,%5,%6,%7}, {%8,%9}, {%0,%1,%2,%3};"
        : "+r"(c[0]), "+r"(c[1]), "+r"(c[2]), "+r"(c[3])
        : "r"(a[0]), "r"(a[1]), "r"(a[2]), "r"(a[3]), "r"(b0), "r"(b1));
}

// ---------------------------------------------------------------------------
// Kernel 1: weight prep.  Per co: mean, unbiased std, sw = 2^round(log2(mean|bw|)),
// store sign(bw) as s8 in [tap][co][ci] layout, sw separately.
// ---------------------------------------------------------------------------
__global__ void __launch_bounds__(256) kwprep(const float* __restrict__ w){
    int co = blockIdx.x;
    int t  = threadIdx.x;
    const float* wr = w + (size_t)co * KTOT;
    __shared__ float red[256];

    float v[9];
    #pragma unroll
    for (int j = 0; j < 9; j++) v[j] = wr[t + j*256];

    float s = 0.f;
    #pragma unroll
    for (int j = 0; j < 9; j++) s += v[j];
    red[t] = s; __syncthreads();
    for (int off = 128; off > 0; off >>= 1){ if (t < off) red[t] += red[t+off]; __syncthreads(); }
    float mean = red[0] / 2304.0f;
    __syncthreads();

    float ss = 0.f, sa = 0.f;
    #pragma unroll
    for (int j = 0; j < 9; j++){ float d = v[j] - mean; ss += d*d; sa += fabsf(d); }
    red[t] = ss; __syncthreads();
    for (int off = 128; off > 0; off >>= 1){ if (t < off) red[t] += red[t+off]; __syncthreads(); }
    float stdv = sqrtf(red[0] / 2303.0f);   // ddof=1
    __syncthreads();
    red[t] = sa; __syncthreads();
    for (int off = 128; off > 0; off >>= 1){ if (t < off) red[t] += red[t+off]; __syncthreads(); }
    float meanabs = red[0] / (stdv * 2304.0f);      // mean|bw|
    float sw = exp2f(rintf(log2f(meanabs)));        // round-half-even, matches jnp.round
    if (t == 0) g_sw[co] = sw;

    #pragma unroll
    for (int j = 0; j < 9; j++){
        int idx = t + j*256;                // = ci*9 + tap  (OIHW inner layout)
        int ci = idx / 9, tap = idx % 9;
        float d = v[j] - mean;
        int8_t b = (d > 0.f) ? 1 : ((d < 0.f) ? -1 : 0);   // sign(0)=0 per jnp.sign
        g_wq[(size_t)tap*65536 + (size_t)co*256 + ci] = b;
    }
}

// ---------------------------------------------------------------------------
// Kernel 2: binarize activations, NCHW fp32 -> NHWC s8 (SMEM transpose)
// ---------------------------------------------------------------------------
__global__ void __launch_bounds__(256) kbin(const float* __restrict__ x){
    __shared__ __align__(16) int8_t sm[HWD][272];
    int h = blockIdx.x, n = blockIdx.y;
    int t = threadIdx.x, wid = t >> 5, lane = t & 31;

    for (int ci = wid; ci < C; ci += 8){
        for (int w = lane; w < HWD; w += 32){
            float v = x[(((size_t)n*C + ci)*HWD + h)*HWD + w];
            sm[w][ci] = (v > 0.f) ? 1 : ((v < 0.f) ? -1 : 0);
        }
    }
    __syncthreads();
    for (int w = wid; w < HWD; w += 8){
        uint2 val = *reinterpret_cast<const uint2*>(&sm[w][lane*8]);
        *reinterpret_cast<uint2*>(&g_ba[(((size_t)(n*HWD + h)*HWD + w) << 8) + lane*8]) = val;
    }
}

// ---------------------------------------------------------------------------
// Kernel 2b: deterministic scratch init (also shifts launch index so the
// harness's ncu capture slot lands on kconv next round)
// ---------------------------------------------------------------------------
__global__ void kzinit(){
    int t = threadIdx.x;
    #pragma unroll
    for (int i = 0; i < 8; i++){ g_psum[t*8 + i] = 0.f; g_psq[t*8 + i] = 0.f; }
}

// ---------------------------------------------------------------------------
// Kernel 3: conv as 9-tap accumulated int8 mma.sync GEMM
//   CTA: 128 spatial (M) x 64 co (N); K = 2304 in 36 chunks of 64.
//   8 warps in 4(M) x 2(N); warp tile 32x32 -> acc = 32 regs (no spills).
// ---------------------------------------------------------------------------
DINL void load_stage(int k2, int s, uint32_t sb, int t, int n, int ph, int pw,
                     bool prow, int coBase){
    int tap = k2 >> 2, kc = k2 & 3;
    int h2 = ph + tap/3 - 1;
    int w2 = pw + tap%3 - 1;
    bool valid = prow && ((unsigned)h2 < (unsigned)HWD) && ((unsigned)w2 < (unsigned)HWD);
    int r = t >> 1, half = t & 1;

    // A: 128 rows x 64B. Each thread: 32B (2x cp16).
    size_t aoff = valid ? ((((size_t)n*HWD + h2)*HWD + w2)*256 + kc*64) : 0;
    const char* asrc = (const char*)g_ba + aoff + half*32;
    uint32_t abase = sb + s*STAGE_BYTES + r*80 + half*32;
    cp16(abase,      asrc,      valid);
    cp16(abase + 16, asrc + 16, valid);

    // B: 64 rows x 64B. Each thread: 16B (1x cp16).
    int br = t >> 2, bq = t & 3;
    const char* bsrc = (const char*)g_wq + (size_t)tap*65536
                     + (size_t)(coBase + br)*256 + kc*64 + bq*16;
    uint32_t bbase = sb + s*STAGE_BYTES + A_SM + br*80 + bq*16;
    cp16(bbase, bsrc, true);
    CP_COMMIT();
}

__global__ void __launch_bounds__(256, 2) kconv(){
    extern __shared__ __align__(128) char smem[];
    uint32_t sb = smem_u32(smem);
    int t = threadIdx.x, lane = t & 31, wid = t >> 5;
    int n      = blockIdx.z;
    int coBase = blockIdx.y * BN;
    int p0     = blockIdx.x * BM;
    int wm = wid & 3, wn = wid >> 2;

    // geometry for this thread's A load row
    int r  = t >> 1;
    int p  = p0 + r;
    int ph = p / HWD, pw = p % HWD;
    bool prow = p < SP;

    // ldmatrix per-lane address components (verified s8 fragment mappings)
    int arow  = (lane & 7) + ((lane >> 3) & 1) * 8;
    int akoff = (lane >> 4) * 16;
    int brow  = (lane & 7) + (lane >> 4) * 8;
    int bkoff = ((lane >> 3) & 1) * 16;

    int acc[2][4][4];
    #pragma unroll
    for (int mf = 0; mf < 2; mf++)
        #pragma unroll
        for (int nf = 0; nf < 4; nf++)
            #pragma unroll
            for (int q = 0; q < 4; q++) acc[mf][nf][q] = 0;

    // prologue: stages 0..2
    load_stage(0, 0, sb, t, n, ph, pw, prow, coBase);
    load_stage(1, 1, sb, t, n, ph, pw, prow, coBase);
    load_stage(2, 2, sb, t, n, ph, pw, prow, coBase);

    for (int k = 0; k < NSTEP; k++){
        int s = k & 3;
        CP_WAIT2();                 // stage k resident
        __syncthreads();            // all warps done reading stage being overwritten
        if (k + 3 < NSTEP) load_stage(k + 3, (k + 3) & 3, sb, t, n, ph, pw, prow, coBase);
        else               CP_COMMIT();   // keep group counts uniform

        uint32_t sAb = sb + s*STAGE_BYTES;
        uint32_t sBb = sAb + A_SM;
        #pragma unroll
        for (int ks = 0; ks < 2; ks++){
            uint32_t a[2][4], b[2][4];
            #pragma unroll
            for (int mf = 0; mf < 2; mf++)
                ldmx4(a[mf], sAb + (uint32_t)(wm*32 + mf*16 + arow)*80 + ks*32 + akoff);
            #pragma unroll
            for (int nf2 = 0; nf2 < 2; nf2++)
                ldmx4(b[nf2], sBb + (uint32_t)(wn*32 + nf2*16 + brow)*80 + ks*32 + bkoff);
            #pragma unroll
            for (int mf = 0; mf < 2; mf++)
                #pragma unroll
                for (int nf = 0; nf < 4; nf++)
                    mma_s8(acc[mf][nf], a[mf],
                           b[nf >> 1][(nf & 1)*2], b[nf >> 1][(nf & 1)*2 + 1]);
        }
    }

    // epilogue: s32 -> f32 (exact), NCHW stores in 32B runs
    int g = lane >> 2, tig = lane & 3;
    float* ybase = g_y + (size_t)n * C * SP;
    #pragma unroll
    for (int mf = 0; mf < 2; mf++){
        #pragma unroll
        for (int nf = 0; nf < 4; nf++){
            int co = coBase + wn*32 + nf*8 + tig*2;
            int pp = p0 + wm*32 + mf*16 + g;
            if (pp < SP){
                ybase[(size_t)co     * SP + pp] = __int2float_rn(acc[mf][nf][0]);
                ybase[(size_t)(co+1) * SP + pp] = __int2float_rn(acc[mf][nf][1]);
            }
            if (pp + 8 < SP){
                ybase[(size_t)co     * SP + pp + 8] = __int2float_rn(acc[mf][nf][2]);
                ybase[(size_t)(co+1) * SP + pp + 8] = __int2float_rn(acc[mf][nf][3]);
            }
        }
    }
}

// ---------------------------------------------------------------------------
// Kernel 4: deterministic per-channel partial sums over z  (grid: 8 x 256)
// ---------------------------------------------------------------------------
__global__ void __launch_bounds__(256) kstats(){
    int cx = blockIdx.x;      // 0..7 -> 4 images each
    int co = blockIdx.y;
    int t = threadIdx.x;
    float s = 0.f, q = 0.f;
    for (int nn = cx*4; nn < cx*4 + 4; nn++){
        const float* pl = g_y + ((size_t)nn * C + co) * SP;
        for (int i = t; i < SP; i += 256){ float v = pl[i]; s += v; q += v*v; }
    }
    __shared__ float rs[256], rq[256];
    rs[t] = s; rq[t] = q; __syncthreads();
    for (int off = 128; off > 0; off >>= 1){
        if (t < off){ rs[t] += rs[t+off]; rq[t] += rq[t+off]; }
        __syncthreads();
    }
    if (t == 0){ g_psum[co*8 + cx] = rs[0]; g_psq[co*8 + cx] = rq[0]; }
}

// ---------------------------------------------------------------------------
// Kernel 5: finalize BN scale/bias, folding sw exactly (y = sw*z)
// ---------------------------------------------------------------------------
__global__ void kbnp(const float* __restrict__ gamma, const float* __restrict__ beta){
    int co = threadIdx.x;
    float s = 0.f, q = 0.f;
    #pragma unroll
    for (int i = 0; i < 8; i++){ s += g_psum[co*8 + i]; q += g_psq[co*8 + i]; }
    float sw = g_sw[co];
    float mean_z = s / (float)NSP;
    float var_z  = q / (float)NSP - mean_z*mean_z;        // biased (ddof=0)
    float var_y  = sw*sw*var_z;
    float sc = gamma[co] * rsqrtf(var_y + 1e-5f);
    g_scale[co] = sw * sc;                                // applied to z
    g_bias[co]  = beta[co] - sw * mean_z * sc;
}

// ---------------------------------------------------------------------------
// Kernel 6: apply BN + hardtanh, vectorized float4
// ---------------------------------------------------------------------------
__global__ void __launch_bounds__(256) kapply(float* __restrict__ out){
    size_t i4 = (size_t)blockIdx.x * 256 + threadIdx.x;   // TOT/4 = 6,422,528 exact
    int co = (int)((i4 / (SP/4)) & 255);
    float sc = g_scale[co], b = g_bias[co];
    float4 v = reinterpret_cast<const float4*>(g_y)[i4];
    float4 r;
    r.x = fminf(fmaxf(v.x*sc + b, -1.f), 1.f);
    r.y = fminf(fmaxf(v.y*sc + b, -1.f), 1.f);
    r.z = fminf(fmaxf(v.z*sc + b, -1.f), 1.f);
    r.w = fminf(fmaxf(v.w*sc + b, -1.f), 1.f);
    reinterpret_cast<float4*>(out)[i4] = r;
}

// ---------------------------------------------------------------------------
extern "C" void kernel_launch(void* const* d_in, const int* in_sizes, int n_in,
                              void* d_out, int out_size){
    const float* x     = (const float*)d_in[0];
    const float* w     = (const float*)d_in[1];
    const float* gamma = (const float*)d_in[2];
    const float* beta  = (const float*)d_in[3];
    float* out = (float*)d_out;

    cudaFuncSetAttribute(kconv, cudaFuncAttributeMaxDynamicSharedMemorySize, SMEM_TOTAL);

    kwprep<<<256, 256>>>(w);
    kbin  <<<dim3(HWD, NB), 256>>>(x);
    kzinit<<<1, 256>>>();
    kconv <<<dim3((SP + BM - 1)/BM, C/BN, NB), 256, SMEM_TOTAL>>>();
    kstats<<<dim3(8, 256), 256>>>();
    kbnp  <<<1, 256>>>(gamma, beta);
    kapply<<<(unsigned)(TOT/4/256), 256>>>(out);
}

// round 11
// speedup vs baseline: 1.2305x; 1.2111x over previous
#include <cuda_runtime.h>
#include <cuda_bf16.h>
#include <cstdint>
#include <math.h>

// ---------------------------------------------------------------------------
// Problem sizes
// ---------------------------------------------------------------------------
#define NB   32
#define C    256
#define HWD  56
#define SP   (HWD*HWD)          // 3136
#define NSP  (NB*SP)            // 100352
#define TOT  ((size_t)NB*C*SP)  // 25,690,112
#define KTOT (C*9)              // 2304

#define NSB  8                  // images 0..7 -> s8 kernel, 8..31 -> bf16 kernel

// s8 conv tiling (proven round-10 config)
#define BM 128
#define BN 64
#define NSTEP 36                // 9 taps * 4 ci-chunks of 64
#define A_SM 10240              // 128 rows * 80B
#define B_SM 5120               // 64 rows * 80B
#define STAGE_BYTES (A_SM + B_SM)           // 15360
#define SMEM_S8 (4*STAGE_BYTES)             // 61440

// bf16 conv tiling: rows are 128B data + 16B pad = 144B
#define A_SMH (128*144)         // 18432
#define B_SMH (64*144)          // 9216
#define STAGE_H (A_SMH + B_SMH) // 27648
#define SMEM_H  (3*STAGE_H)     // 82944  (3 stages, 2 CTAs/SM)

#define DINL __device__ __forceinline__

// ---------------------------------------------------------------------------
// Device scratch
// ---------------------------------------------------------------------------
__device__ int8_t        g_ba[(size_t)NSB*SP*C];          // s8 acts, images 0..7
__device__ __nv_bfloat16 g_bb[(size_t)(NB-NSB)*SP*C];     // bf16 acts, images 8..31
__device__ int8_t        g_wq [9*256*256];                // sign(bw) s8,  [tap][co][ci]
__device__ __nv_bfloat16 g_wqh[9*256*256];                // sign(bw) bf16,[tap][co][ci]
__device__ float  g_sw[256];
__device__ float  g_y [TOT];                              // conv int result z (f32), NCHW
__device__ float  g_psum[256*8];
__device__ float  g_psq [256*8];
__device__ float  g_scale[256];
__device__ float  g_bias [256];

// ---------------------------------------------------------------------------
// PTX helpers (arch-portable: cp.async / ldmatrix / mma.sync)
// ---------------------------------------------------------------------------
DINL uint32_t smem_u32(const void* p){
    uint32_t a;
    asm("{ .reg .u64 t; cvta.to.shared.u64 t, %1; cvt.u32.u64 %0, t; }" : "=r"(a) : "l"(p));
    return a;
}

DINL void cp16(uint32_t dst, const void* src, bool pred){
    int sz = pred ? 16 : 0;
    asm volatile("cp.async.cg.shared.global [%0], [%1], 16, %2;\n"
                 :: "r"(dst), "l"(src), "r"(sz) : "memory");
}
#define CP_COMMIT() asm volatile("cp.async.commit_group;\n" ::: "memory")
#define CP_WAIT2()  asm volatile("cp.async.wait_group 2;\n" ::: "memory")
#define CP_WAIT1()  asm volatile("cp.async.wait_group 1;\n" ::: "memory")

DINL void ldmx4(uint32_t* r, uint32_t addr){
    asm volatile("ldmatrix.sync.aligned.m8n8.x4.shared.b16 {%0,%1,%2,%3}, [%4];"
                 : "=r"(r[0]), "=r"(r[1]), "=r"(r[2]), "=r"(r[3]) : "r"(addr));
}

DINL void mma_s8(int* c, const uint32_t* a, uint32_t b0, uint32_t b1){
    asm volatile(
        "mma.sync.aligned.m16n8k32.row.col.s32.s8.s8.s32 "
        "{%0,%1,%2,%3}, {%4,%5,%6,%7}, {%8,%9}, {%0,%1,%2,%3};"
        : "+r"(c[0]), "+r"(c[1]), "+r"(c[2]), "+r"(c[3])
        : "r"(a[0]), "r"(a[1]), "r"(a[2]), "r"(a[3]), "r"(b0), "r"(b1));
}

DINL void mma_bf16(float* c, const uint32_t* a, uint32_t b0, uint32_t b1){
    asm volatile(
        "mma.sync.aligned.m16n8k16.row.col.f32.bf16.bf16.f32 "
        "{%0,%1,%2,%3}, {%4,%5,%6,%7}, {%8,%9}, {%0,%1,%2,%3};"
        : "+f"(c[0]), "+f"(c[1]), "+f"(c[2]), "+f"(c[3])
        : "r"(a[0]), "r"(a[1]), "r"(a[2]), "r"(a[3]), "r"(b0), "r"(b1));
}

DINL uint16_t sgn_bf16(int8_t v){           // ±1 / 0 -> bf16 bits
    return (v > 0) ? 0x3F80u : ((v < 0) ? 0xBF80u : 0u);
}

// ---------------------------------------------------------------------------
// Kernel 1: weight prep (mean, unbiased std, sw; write s8 + bf16 sign planes)
// ---------------------------------------------------------------------------
__global__ void __launch_bounds__(256) kwprep(const float* __restrict__ w){
    int co = blockIdx.x;
    int t  = threadIdx.x;
    const float* wr = w + (size_t)co * KTOT;
    __shared__ float red[256];

    float v[9];
    #pragma unroll
    for (int j = 0; j < 9; j++) v[j] = wr[t + j*256];

    float s = 0.f;
    #pragma unroll
    for (int j = 0; j < 9; j++) s += v[j];
    red[t] = s; __syncthreads();
    for (int off = 128; off > 0; off >>= 1){ if (t < off) red[t] += red[t+off]; __syncthreads(); }
    float mean = red[0] / 2304.0f;
    __syncthreads();

    float ss = 0.f, sa = 0.f;
    #pragma unroll
    for (int j = 0; j < 9; j++){ float d = v[j] - mean; ss += d*d; sa += fabsf(d); }
    red[t] = ss; __syncthreads();
    for (int off = 128; off > 0; off >>= 1){ if (t < off) red[t] += red[t+off]; __syncthreads(); }
    float stdv = sqrtf(red[0] / 2303.0f);   // ddof=1
    __syncthreads();
    red[t] = sa; __syncthreads();
    for (int off = 128; off > 0; off >>= 1){ if (t < off) red[t] += red[t+off]; __syncthreads(); }
    float meanabs = red[0] / (stdv * 2304.0f);
    float sw = exp2f(rintf(log2f(meanabs)));
    if (t == 0) g_sw[co] = sw;

    #pragma unroll
    for (int j = 0; j < 9; j++){
        int idx = t + j*256;                // = ci*9 + tap
        int ci = idx / 9, tap = idx % 9;
        float d = v[j] - mean;
        int8_t b = (d > 0.f) ? 1 : ((d < 0.f) ? -1 : 0);
        size_t o = (size_t)tap*65536 + (size_t)co*256 + ci;
        g_wq[o] = b;
        reinterpret_cast<uint16_t*>(g_wqh)[o] = sgn_bf16(b);
    }
}

// ---------------------------------------------------------------------------
// Kernel 2: binarize, NCHW fp32 -> NHWC (s8 for n<NSB, bf16 otherwise)
// ---------------------------------------------------------------------------
__global__ void __launch_bounds__(256) kbin(const float* __restrict__ x){
    __shared__ __align__(16) int8_t sm[HWD][272];
    int h = blockIdx.x, n = blockIdx.y;
    int t = threadIdx.x, wid = t >> 5, lane = t & 31;

    for (int ci = wid; ci < C; ci += 8){
        for (int w = lane; w < HWD; w += 32){
            float v = x[(((size_t)n*C + ci)*HWD + h)*HWD + w];
            sm[w][ci] = (v > 0.f) ? 1 : ((v < 0.f) ? -1 : 0);
        }
    }
    __syncthreads();
    if (n < NSB){
        for (int w = wid; w < HWD; w += 8){
            uint2 val = *reinterpret_cast<const uint2*>(&sm[w][lane*8]);
            *reinterpret_cast<uint2*>(&g_ba[(((size_t)(n*HWD + h)*HWD + w) << 8) + lane*8]) = val;
        }
    } else {
        int nn = n - NSB;
        for (int w = wid; w < HWD; w += 8){
            const int8_t* src = &sm[w][lane*8];
            uint32_t pk[4];
            #pragma unroll
            for (int j = 0; j < 4; j++){
                uint32_t lo = sgn_bf16(src[2*j]);
                uint32_t hi = sgn_bf16(src[2*j+1]);
                pk[j] = lo | (hi << 16);
            }
            *reinterpret_cast<uint4*>(
                &g_bb[(((size_t)(nn*HWD + h)*HWD + w) << 8) + lane*8]) =
                *reinterpret_cast<uint4*>(pk);
        }
    }
}

// ---------------------------------------------------------------------------
// Kernel 3a: s8 conv (images 0..NSB-1) — proven round-10 kernel
// ---------------------------------------------------------------------------
DINL void load_stage_s8(int k2, int s, uint32_t sb, int t, int n, int ph, int pw,
                        bool prow, int coBase){
    int tap = k2 >> 2, kc = k2 & 3;
    int h2 = ph + tap/3 - 1;
    int w2 = pw + tap%3 - 1;
    bool valid = prow && ((unsigned)h2 < (unsigned)HWD) && ((unsigned)w2 < (unsigned)HWD);
    int r = t >> 1, half = t & 1;

    size_t aoff = valid ? ((((size_t)n*HWD + h2)*HWD + w2)*256 + kc*64) : 0;
    const char* asrc = (const char*)g_ba + aoff + half*32;
    uint32_t abase = sb + s*STAGE_BYTES + r*80 + half*32;
    cp16(abase,      asrc,      valid);
    cp16(abase + 16, asrc + 16, valid);

    int br = t >> 2, bq = t & 3;
    const char* bsrc = (const char*)g_wq + (size_t)tap*65536
                     + (size_t)(coBase + br)*256 + kc*64 + bq*16;
    uint32_t bbase = sb + s*STAGE_BYTES + A_SM + br*80 + bq*16;
    cp16(bbase, bsrc, true);
    CP_COMMIT();
}

__global__ void __launch_bounds__(256, 2) kconv_s8(){
    extern __shared__ __align__(128) char smem[];
    uint32_t sb = smem_u32(smem);
    int t = threadIdx.x, lane = t & 31, wid = t >> 5;
    int n      = blockIdx.z;
    int coBase = blockIdx.y * BN;
    int p0     = blockIdx.x * BM;
    int wm = wid & 3, wn = wid >> 2;

    int r  = t >> 1;
    int p  = p0 + r;
    int ph = p / HWD, pw = p % HWD;
    bool prow = p < SP;

    int arow  = (lane & 7) + ((lane >> 3) & 1) * 8;
    int akoff = (lane >> 4) * 16;
    int brow  = (lane & 7) + (lane >> 4) * 8;
    int bkoff = ((lane >> 3) & 1) * 16;

    int acc[2][4][4];
    #pragma unroll
    for (int mf = 0; mf < 2; mf++)
        #pragma unroll
        for (int nf = 0; nf < 4; nf++)
            #pragma unroll
            for (int q = 0; q < 4; q++) acc[mf][nf][q] = 0;

    load_stage_s8(0, 0, sb, t, n, ph, pw, prow, coBase);
    load_stage_s8(1, 1, sb, t, n, ph, pw, prow, coBase);
    load_stage_s8(2, 2, sb, t, n, ph, pw, prow, coBase);

    for (int k = 0; k < NSTEP; k++){
        int s = k & 3;
        CP_WAIT2();
        __syncthreads();
        if (k + 3 < NSTEP) load_stage_s8(k + 3, (k + 3) & 3, sb, t, n, ph, pw, prow, coBase);
        else               CP_COMMIT();

        uint32_t sAb = sb + s*STAGE_BYTES;
        uint32_t sBb = sAb + A_SM;
        #pragma unroll
        for (int ks = 0; ks < 2; ks++){
            uint32_t a[2][4], b[2][4];
            #pragma unroll
            for (int mf = 0; mf < 2; mf++)
                ldmx4(a[mf], sAb + (uint32_t)(wm*32 + mf*16 + arow)*80 + ks*32 + akoff);
            #pragma unroll
            for (int nf2 = 0; nf2 < 2; nf2++)
                ldmx4(b[nf2], sBb + (uint32_t)(wn*32 + nf2*16 + brow)*80 + ks*32 + bkoff);
            #pragma unroll
            for (int mf = 0; mf < 2; mf++)
                #pragma unroll
                for (int nf = 0; nf < 4; nf++)
                    mma_s8(acc[mf][nf], a[mf],
                           b[nf >> 1][(nf & 1)*2], b[nf >> 1][(nf & 1)*2 + 1]);
        }
    }

    int g = lane >> 2, tig = lane & 3;
    float* ybase = g_y + (size_t)n * C * SP;
    #pragma unroll
    for (int mf = 0; mf < 2; mf++){
        #pragma unroll
        for (int nf = 0; nf < 4; nf++){
            int co = coBase + wn*32 + nf*8 + tig*2;
            int pp = p0 + wm*32 + mf*16 + g;
            if (pp < SP){
                ybase[(size_t)co     * SP + pp] = __int2float_rn(acc[mf][nf][0]);
                ybase[(size_t)(co+1) * SP + pp] = __int2float_rn(acc[mf][nf][1]);
            }
            if (pp + 8 < SP){
                ybase[(size_t)co     * SP + pp + 8] = __int2float_rn(acc[mf][nf][2]);
                ybase[(size_t)(co+1) * SP + pp + 8] = __int2float_rn(acc[mf][nf][3]);
            }
        }
    }
}

// ---------------------------------------------------------------------------
// Kernel 3b: bf16 conv (images NSB..31). Same 128x64 CTA tile; rows 144B.
//   K-chunk 64 -> 4 mma k16 sub-steps; HMMA f32 accum (bit-exact for +-1).
// ---------------------------------------------------------------------------
DINL void load_stage_h(int k2, int s, uint32_t sb, int t, int n, int ph, int pw,
                       bool prow, int coBase){
    int tap = k2 >> 2, kc = k2 & 3;
    int h2 = ph + tap/3 - 1;
    int w2 = pw + tap%3 - 1;
    bool valid = prow && ((unsigned)h2 < (unsigned)HWD) && ((unsigned)w2 < (unsigned)HWD);
    int r = t >> 1, half = t & 1;

    // A: 128 rows x 128B. Each thread 64B (4x cp16).
    size_t aoff = valid ? ((((size_t)(n-NSB)*HWD + h2)*HWD + w2)*256 + kc*64) : 0;
    const char* asrc = (const char*)g_bb + aoff*2 + half*64;
    uint32_t abase = sb + s*STAGE_H + r*144 + half*64;
    #pragma unroll
    for (int j = 0; j < 4; j++) cp16(abase + j*16, asrc + j*16, valid);

    // B: 64 rows x 128B. Each thread 32B (2x cp16).
    int br = t >> 2, bq = t & 3;
    const char* bsrc = (const char*)g_wqh + ((size_t)tap*65536
                     + (size_t)(coBase + br)*256 + kc*64)*2 + bq*32;
    uint32_t bbase = sb + s*STAGE_H + A_SMH + br*144 + bq*32;
    cp16(bbase,      bsrc,      true);
    cp16(bbase + 16, bsrc + 16, true);
    CP_COMMIT();
}

__global__ void __launch_bounds__(256, 2) kconv_h(){
    extern __shared__ __align__(128) char smem[];
    uint32_t sb = smem_u32(smem);
    int t = threadIdx.x, lane = t & 31, wid = t >> 5;
    int n      = blockIdx.z + NSB;
    int coBase = blockIdx.y * BN;
    int p0     = blockIdx.x * BM;
    int wm = wid & 3, wn = wid >> 2;

    int r  = t >> 1;
    int p  = p0 + r;
    int ph = p / HWD, pw = p % HWD;
    bool prow = p < SP;

    // same byte-level fragment mappings as s8 (k16 bf16 = 32B, like k32 s8)
    int arow  = (lane & 7) + ((lane >> 3) & 1) * 8;
    int akoff = (lane >> 4) * 16;
    int brow  = (lane & 7) + (lane >> 4) * 8;
    int bkoff = ((lane >> 3) & 1) * 16;

    float acc[2][4][4];
    #pragma unroll
    for (int mf = 0; mf < 2; mf++)
        #pragma unroll
        for (int nf = 0; nf < 4; nf++)
            #pragma unroll
            for (int q = 0; q < 4; q++) acc[mf][nf][q] = 0.f;

    load_stage_h(0, 0, sb, t, n, ph, pw, prow, coBase);
    load_stage_h(1, 1, sb, t, n, ph, pw, prow, coBase);

    for (int k = 0; k < NSTEP; k++){
        int s = k % 3;
        CP_WAIT1();                 // stage k resident
        __syncthreads();
        if (k + 2 < NSTEP) load_stage_h(k + 2, (k + 2) % 3, sb, t, n, ph, pw, prow, coBase);
        else               CP_COMMIT();

        uint32_t sAb = sb + s*STAGE_H;
        uint32_t sBb = sAb + A_SMH;
        #pragma unroll
        for (int ks = 0; ks < 4; ks++){
            uint32_t a[2][4], b[2][4];
            #pragma unroll
            for (int mf = 0; mf < 2; mf++)
                ldmx4(a[mf], sAb + (uint32_t)(wm*32 + mf*16 + arow)*144 + ks*32 + akoff);
            #pragma unroll
            for (int nf2 = 0; nf2 < 2; nf2++)
                ldmx4(b[nf2], sBb + (uint32_t)(wn*32 + nf2*16 + brow)*144 + ks*32 + bkoff);
            #pragma unroll
            for (int mf = 0; mf < 2; mf++)
                #pragma unroll
                for (int nf = 0; nf < 4; nf++)
                    mma_bf16(acc[mf][nf], a[mf],
                             b[nf >> 1][(nf & 1)*2], b[nf >> 1][(nf & 1)*2 + 1]);
        }
    }

    int g = lane >> 2, tig = lane & 3;
    float* ybase = g_y + (size_t)n * C * SP;
    #pragma unroll
    for (int mf = 0; mf < 2; mf++){
        #pragma unroll
        for (int nf = 0; nf < 4; nf++){
            int co = coBase + wn*32 + nf*8 + tig*2;
            int pp = p0 + wm*32 + mf*16 + g;
            if (pp < SP){
                ybase[(size_t)co     * SP + pp] = acc[mf][nf][0];
                ybase[(size_t)(co+1) * SP + pp] = acc[mf][nf][1];
            }
            if (pp + 8 < SP){
                ybase[(size_t)co     * SP + pp + 8] = acc[mf][nf][2];
                ybase[(size_t)(co+1) * SP + pp + 8] = acc[mf][nf][3];
            }
        }
    }
}

// ---------------------------------------------------------------------------
// Kernel 4: deterministic per-channel partial sums over z  (grid: 8 x 256)
// ---------------------------------------------------------------------------
__global__ void __launch_bounds__(256) kstats(){
    int cx = blockIdx.x;
    int co = blockIdx.y;
    int t = threadIdx.x;
    float s = 0.f, q = 0.f;
    for (int nn = cx*4; nn < cx*4 + 4; nn++){
        const float* pl = g_y + ((size_t)nn * C + co) * SP;
        for (int i = t; i < SP; i += 256){ float v = pl[i]; s += v; q += v*v; }
    }
    __shared__ float rs[256], rq[256];
    rs[t] = s; rq[t] = q; __syncthreads();
    for (int off = 128; off > 0; off >>= 1){
        if (t < off){ rs[t] += rs[t+off]; rq[t] += rq[t+off]; }
        __syncthreads();
    }
    if (t == 0){ g_psum[co*8 + cx] = rs[0]; g_psq[co*8 + cx] = rq[0]; }
}

// ---------------------------------------------------------------------------
// Kernel 5: finalize BN scale/bias, folding sw exactly (y = sw*z)
// ---------------------------------------------------------------------------
__global__ void kbnp(const float* __restrict__ gamma, const float* __restrict__ beta){
    int co = threadIdx.x;
    float s = 0.f, q = 0.f;
    #pragma unroll
    for (int i = 0; i < 8; i++){ s += g_psum[co*8 + i]; q += g_psq[co*8 + i]; }
    float sw = g_sw[co];
    float mean_z = s / (float)NSP;
    float var_z  = q / (float)NSP - mean_z*mean_z;
    float var_y  = sw*sw*var_z;
    float sc = gamma[co] * rsqrtf(var_y + 1e-5f);
    g_scale[co] = sw * sc;
    g_bias[co]  = beta[co] - sw * mean_z * sc;
}

// ---------------------------------------------------------------------------
// Kernel 6: apply BN + hardtanh, vectorized float4
// ---------------------------------------------------------------------------
__global__ void __launch_bounds__(256) kapply(float* __restrict__ out){
    size_t i4 = (size_t)blockIdx.x * 256 + threadIdx.x;
    int co = (int)((i4 / (SP/4)) & 255);
    float sc = g_scale[co], b = g_bias[co];
    float4 v = reinterpret_cast<const float4*>(g_y)[i4];
    float4 r;
    r.x = fminf(fmaxf(v.x*sc + b, -1.f), 1.f);
    r.y = fminf(fmaxf(v.y*sc + b, -1.f), 1.f);
    r.z = fminf(fmaxf(v.z*sc + b, -1.f), 1.f);
    r.w = fminf(fmaxf(v.w*sc + b, -1.f), 1.f);
    reinterpret_cast<float4*>(out)[i4] = r;
}

// ---------------------------------------------------------------------------
extern "C" void kernel_launch(void* const* d_in, const int* in_sizes, int n_in,
                              void* d_out, int out_size){
    const float* x     = (const float*)d_in[0];
    const float* w     = (const float*)d_in[1];
    const float* gamma = (const float*)d_in[2];
    const float* beta  = (const float*)d_in[3];
    float* out = (float*)d_out;

    cudaFuncSetAttribute(kconv_s8, cudaFuncAttributeMaxDynamicSharedMemorySize, SMEM_S8);
    cudaFuncSetAttribute(kconv_h,  cudaFuncAttributeMaxDynamicSharedMemorySize, SMEM_H);

    kwprep  <<<256, 256>>>(w);
    kbin    <<<dim3(HWD, NB), 256>>>(x);
    kconv_s8<<<dim3((SP + BM - 1)/BM, C/BN, NSB),      256, SMEM_S8>>>();
    kconv_h <<<dim3((SP + BM - 1)/BM, C/BN, NB - NSB), 256, SMEM_H>>>();   // 4th launch: ncu slot
    kstats  <<<dim3(8, 256), 256>>>();
    kbnp    <<<1, 256>>>(gamma, beta);
    kapply  <<<(unsigned)(TOT/4/256), 256>>>(out);
}

// round 12
// speedup vs baseline: 1.3931x; 1.1322x over previous
#include <cuda_runtime.h>
#include <cuda_bf16.h>
#include <cstdint>
#include <math.h>

// ---------------------------------------------------------------------------
// Problem sizes
// ---------------------------------------------------------------------------
#define NB   32
#define C    256
#define HWD  56
#define SP   (HWD*HWD)          // 3136
#define NSP  (NB*SP)            // 100352
#define TOT  ((size_t)NB*C*SP)  // 25,690,112
#define KTOT (C*9)              // 2304

// bf16 conv tiling: CTA 128M x 64N, K-chunk 64 (4x mma k16), rows 128B+16B pad
#define BM 128
#define BN 64
#define NSTEP 36                // 9 taps * 4 ci-chunks of 64
#define STAGES 4
#define A_SMH (128*144)         // 18432
#define B_SMH (64*144)          // 9216
#define STAGE_H (A_SMH + B_SMH) // 27648
#define SMEM_H  (STAGES*STAGE_H)// 110592 (2 CTAs/SM: 221184 < 228KB)

#define DINL __device__ __forceinline__

// ---------------------------------------------------------------------------
// Device scratch
// ---------------------------------------------------------------------------
__device__ __nv_bfloat16 g_bb[(size_t)NB*SP*C];     // binarized acts bf16, NHWC
__device__ __nv_bfloat16 g_wqh[9*256*256];          // sign(bw) bf16, [tap][co][ci]
__device__ float  g_sw[256];
__device__ float  g_y [TOT];                        // conv result z (f32), NCHW
__device__ float  g_psum[256*8];
__device__ float  g_psq [256*8];
__device__ float  g_scale[256];
__device__ float  g_bias [256];

// ---------------------------------------------------------------------------
// PTX helpers (arch-portable: cp.async / ldmatrix / mma.sync)
// ---------------------------------------------------------------------------
DINL uint32_t smem_u32(const void* p){
    uint32_t a;
    asm("{ .reg .u64 t; cvta.to.shared.u64 t, %1; cvt.u32.u64 %0, t; }" : "=r"(a) : "l"(p));
    return a;
}

DINL void cp16(uint32_t dst, const void* src, bool pred){
    int sz = pred ? 16 : 0;
    asm volatile("cp.async.cg.shared.global [%0], [%1], 16, %2;\n"
                 :: "r"(dst), "l"(src), "r"(sz) : "memory");
}
#define CP_COMMIT() asm volatile("cp.async.commit_group;\n" ::: "memory")
#define CP_WAIT2()  asm volatile("cp.async.wait_group 2;\n" ::: "memory")

DINL void ldmx4(uint32_t* r, uint32_t addr){
    asm volatile("ldmatrix.sync.aligned.m8n8.x4.shared.b16 {%0,%1,%2,%3}, [%4];"
                 : "=r"(r[0]), "=r"(r[1]), "=r"(r[2]), "=r"(r[3]) : "r"(addr));
}

DINL void mma_bf16(float* c, const uint32_t* a, uint32_t b0, uint32_t b1){
    asm volatile(
        "mma.sync.aligned.m16n8k16.row.col.f32.bf16.bf16.f32 "
        "{%0,%1,%2,%3}, {%4,%5,%6,%7}, {%8,%9}, {%0,%1,%2,%3};"
        : "+f"(c[0]), "+f"(c[1]), "+f"(c[2]), "+f"(c[3])
        : "r"(a[0]), "r"(a[1]), "r"(a[2]), "r"(a[3]), "r"(b0), "r"(b1));
}

DINL uint16_t sgn_bf16_f(float v){          // sign(x) -> bf16 bits (sign(0)=0)
    return (v > 0.f) ? 0x3F80u : ((v < 0.f) ? 0xBF80u : 0u);
}

// ---------------------------------------------------------------------------
// Kernel 1: weight prep (mean, unbiased std, sw; bf16 sign plane)
// ---------------------------------------------------------------------------
__global__ void __launch_bounds__(256) kwprep(const float* __restrict__ w){
    int co = blockIdx.x;
    int t  = threadIdx.x;
    const float* wr = w + (size_t)co * KTOT;
    __shared__ float red[256];

    float v[9];
    #pragma unroll
    for (int j = 0; j < 9; j++) v[j] = wr[t + j*256];

    float s = 0.f;
    #pragma unroll
    for (int j = 0; j < 9; j++) s += v[j];
    red[t] = s; __syncthreads();
    for (int off = 128; off > 0; off >>= 1){ if (t < off) red[t] += red[t+off]; __syncthreads(); }
    float mean = red[0] / 2304.0f;
    __syncthreads();

    float ss = 0.f, sa = 0.f;
    #pragma unroll
    for (int j = 0; j < 9; j++){ float d = v[j] - mean; ss += d*d; sa += fabsf(d); }
    red[t] = ss; __syncthreads();
    for (int off = 128; off > 0; off >>= 1){ if (t < off) red[t] += red[t+off]; __syncthreads(); }
    float stdv = sqrtf(red[0] / 2303.0f);   // ddof=1
    __syncthreads();
    red[t] = sa; __syncthreads();
    for (int off = 128; off > 0; off >>= 1){ if (t < off) red[t] += red[t+off]; __syncthreads(); }
    float meanabs = red[0] / (stdv * 2304.0f);
    float sw = exp2f(rintf(log2f(meanabs)));
    if (t == 0) g_sw[co] = sw;

    #pragma unroll
    for (int j = 0; j < 9; j++){
        int idx = t + j*256;                // = ci*9 + tap  (OIHW inner layout)
        int ci = idx / 9, tap = idx % 9;
        float d = v[j] - mean;
        size_t o = (size_t)tap*65536 + (size_t)co*256 + ci;
        reinterpret_cast<uint16_t*>(g_wqh)[o] = sgn_bf16_f(d);
    }
}

// ---------------------------------------------------------------------------
// Kernel 2: binarize activations, NCHW fp32 -> NHWC bf16 (SMEM transpose)
// ---------------------------------------------------------------------------
__global__ void __launch_bounds__(256) kbin(const float* __restrict__ x){
    __shared__ __align__(16) uint16_t sm[HWD][264];
    int h = blockIdx.x, n = blockIdx.y;
    int t = threadIdx.x, wid = t >> 5, lane = t & 31;

    for (int ci = wid; ci < C; ci += 8){
        for (int w = lane; w < HWD; w += 32){
            float v = x[(((size_t)n*C + ci)*HWD + h)*HWD + w];
            sm[w][ci] = sgn_bf16_f(v);
        }
    }
    __syncthreads();
    for (int w = wid; w < HWD; w += 8){
        uint4 val = *reinterpret_cast<const uint4*>(&sm[w][lane*8]);
        *reinterpret_cast<uint4*>(
            &g_bb[(((size_t)(n*HWD + h)*HWD + w) << 8) + lane*8]) = val;
    }
}

// ---------------------------------------------------------------------------
// Kernel 2b: deterministic scratch init (keeps ncu 4th-launch slot on kconv_h)
// ---------------------------------------------------------------------------
__global__ void kzinit(){
    int t = threadIdx.x;
    #pragma unroll
    for (int i = 0; i < 8; i++){ g_psum[t*8 + i] = 0.f; g_psq[t*8 + i] = 0.f; }
}

// ---------------------------------------------------------------------------
// Kernel 3: bf16 conv, 9-tap accumulated HMMA GEMM, 4-stage cp.async pipeline
// ---------------------------------------------------------------------------
DINL void load_stage_h(int k2, int s, uint32_t sb, int t, int n, int ph, int pw,
                       bool prow, int coBase){
    int tap = k2 >> 2, kc = k2 & 3;
    int h2 = ph + tap/3 - 1;
    int w2 = pw + tap%3 - 1;
    bool valid = prow && ((unsigned)h2 < (unsigned)HWD) && ((unsigned)w2 < (unsigned)HWD);
    int r = t >> 1, half = t & 1;

    // A: 128 rows x 128B. Each thread 64B (4x cp16).
    size_t aoff = valid ? ((((size_t)n*HWD + h2)*HWD + w2)*256 + kc*64) : 0;
    const char* asrc = (const char*)g_bb + aoff*2 + half*64;
    uint32_t abase = sb + s*STAGE_H + r*144 + half*64;
    #pragma unroll
    for (int j = 0; j < 4; j++) cp16(abase + j*16, asrc + j*16, valid);

    // B: 64 rows x 128B. Each thread 32B (2x cp16).
    int br = t >> 2, bq = t & 3;
    const char* bsrc = (const char*)g_wqh + ((size_t)tap*65536
                     + (size_t)(coBase + br)*256 + kc*64)*2 + bq*32;
    uint32_t bbase = sb + s*STAGE_H + A_SMH + br*144 + bq*32;
    cp16(bbase,      bsrc,      true);
    cp16(bbase + 16, bsrc + 16, true);
    CP_COMMIT();
}

__global__ void __launch_bounds__(256, 2) kconv_h(){
    extern __shared__ __align__(128) char smem[];
    uint32_t sb = smem_u32(smem);
    int t = threadIdx.x, lane = t & 31, wid = t >> 5;
    int n      = blockIdx.z;
    int coBase = blockIdx.y * BN;
    int p0     = blockIdx.x * BM;
    int wm = wid & 3, wn = wid >> 2;

    int r  = t >> 1;
    int p  = p0 + r;
    int ph = p / HWD, pw = p % HWD;
    bool prow = p < SP;

    // ldmatrix lane->address mapping (b16 fragments, k16 = 32B rows)
    int arow  = (lane & 7) + ((lane >> 3) & 1) * 8;
    int akoff = (lane >> 4) * 16;
    int brow  = (lane & 7) + (lane >> 4) * 8;
    int bkoff = ((lane >> 3) & 1) * 16;

    float acc[2][4][4];
    #pragma unroll
    for (int mf = 0; mf < 2; mf++)
        #pragma unroll
        for (int nf = 0; nf < 4; nf++)
            #pragma unroll
            for (int q = 0; q < 4; q++) acc[mf][nf][q] = 0.f;

    // prologue: stages 0..2
    load_stage_h(0, 0, sb, t, n, ph, pw, prow, coBase);
    load_stage_h(1, 1, sb, t, n, ph, pw, prow, coBase);
    load_stage_h(2, 2, sb, t, n, ph, pw, prow, coBase);

    for (int k = 0; k < NSTEP; k++){
        int s = k & 3;
        CP_WAIT2();                 // stage k resident (2 groups still in flight)
        __syncthreads();            // all warps done with stage being overwritten
        if (k + 3 < NSTEP) load_stage_h(k + 3, (k + 3) & 3, sb, t, n, ph, pw, prow, coBase);
        else               CP_COMMIT();   // uniform group counts

        uint32_t sAb = sb + s*STAGE_H;
        uint32_t sBb = sAb + A_SMH;
        #pragma unroll
        for (int ks = 0; ks < 4; ks++){
            uint32_t a[2][4], b[2][4];
            #pragma unroll
            for (int mf = 0; mf < 2; mf++)
                ldmx4(a[mf], sAb + (uint32_t)(wm*32 + mf*16 + arow)*144 + ks*32 + akoff);
            #pragma unroll
            for (int nf2 = 0; nf2 < 2; nf2++)
                ldmx4(b[nf2], sBb + (uint32_t)(wn*32 + nf2*16 + brow)*144 + ks*32 + bkoff);
            #pragma unroll
            for (int mf = 0; mf < 2; mf++)
                #pragma unroll
                for (int nf = 0; nf < 4; nf++)
                    mma_bf16(acc[mf][nf], a[mf],
                             b[nf >> 1][(nf & 1)*2], b[nf >> 1][(nf & 1)*2 + 1]);
        }
    }

    // epilogue: exact integer-valued f32, NCHW stores
    int g = lane >> 2, tig = lane & 3;
    float* ybase = g_y + (size_t)n * C * SP;
    #pragma unroll
    for (int mf = 0; mf < 2; mf++){
        #pragma unroll
        for (int nf = 0; nf < 4; nf++){
            int co = coBase + wn*32 + nf*8 + tig*2;
            int pp = p0 + wm*32 + mf*16 + g;
            if (pp < SP){
                ybase[(size_t)co     * SP + pp] = acc[mf][nf][0];
                ybase[(size_t)(co+1) * SP + pp] = acc[mf][nf][1];
            }
            if (pp + 8 < SP){
                ybase[(size_t)co     * SP + pp + 8] = acc[mf][nf][2];
                ybase[(size_t)(co+1) * SP + pp + 8] = acc[mf][nf][3];
            }
        }
    }
}

// ---------------------------------------------------------------------------
// Kernel 4: deterministic per-channel partial sums over z  (grid: 8 x 256)
// ---------------------------------------------------------------------------
__global__ void __launch_bounds__(256) kstats(){
    int cx = blockIdx.x;
    int co = blockIdx.y;
    int t = threadIdx.x;
    float s = 0.f, q = 0.f;
    for (int nn = cx*4; nn < cx*4 + 4; nn++){
        const float* pl = g_y + ((size_t)nn * C + co) * SP;
        for (int i = t; i < SP; i += 256){ float v = pl[i]; s += v; q += v*v; }
    }
    __shared__ float rs[256], rq[256];
    rs[t] = s; rq[t] = q; __syncthreads();
    for (int off = 128; off > 0; off >>= 1){
        if (t < off){ rs[t] += rs[t+off]; rq[t] += rq[t+off]; }
        __syncthreads();
    }
    if (t == 0){ g_psum[co*8 + cx] = rs[0]; g_psq[co*8 + cx] = rq[0]; }
}

// ---------------------------------------------------------------------------
// Kernel 5: finalize BN scale/bias, folding sw exactly (y = sw*z)
// ---------------------------------------------------------------------------
__global__ void kbnp(const float* __restrict__ gamma, const float* __restrict__ beta){
    int co = threadIdx.x;
    float s = 0.f, q = 0.f;
    #pragma unroll
    for (int i = 0; i < 8; i++){ s += g_psum[co*8 + i]; q += g_psq[co*8 + i]; }
    float sw = g_sw[co];
    float mean_z = s / (float)NSP;
    float var_z  = q / (float)NSP - mean_z*mean_z;
    float var_y  = sw*sw*var_z;
    float sc = gamma[co] * rsqrtf(var_y + 1e-5f);
    g_scale[co] = sw * sc;
    g_bias[co]  = beta[co] - sw * mean_z * sc;
}

// ---------------------------------------------------------------------------
// Kernel 6: apply BN + hardtanh, vectorized float4
// ---------------------------------------------------------------------------
__global__ void __launch_bounds__(256) kapply(float* __restrict__ out){
    size_t i4 = (size_t)blockIdx.x * 256 + threadIdx.x;
    int co = (int)((i4 / (SP/4)) & 255);
    float sc = g_scale[co], b = g_bias[co];
    float4 v = reinterpret_cast<const float4*>(g_y)[i4];
    float4 r;
    r.x = fminf(fmaxf(v.x*sc + b, -1.f), 1.f);
    r.y = fminf(fmaxf(v.y*sc + b, -1.f), 1.f);
    r.z = fminf(fmaxf(v.z*sc + b, -1.f), 1.f);
    r.w = fminf(fmaxf(v.w*sc + b, -1.f), 1.f);
    reinterpret_cast<float4*>(out)[i4] = r;
}

// ---------------------------------------------------------------------------
extern "C" void kernel_launch(void* const* d_in, const int* in_sizes, int n_in,
                              void* d_out, int out_size){
    const float* x     = (const float*)d_in[0];
    const float* w     = (const float*)d_in[1];
    const float* gamma = (const float*)d_in[2];
    const float* beta  = (const float*)d_in[3];
    float* out = (float*)d_out;

    cudaFuncSetAttribute(kconv_h, cudaFuncAttributeMaxDynamicSharedMemorySize, SMEM_H);

    kwprep <<<256, 256>>>(w);
    kbin   <<<dim3(HWD, NB), 256>>>(x);
    kzinit <<<1, 256>>>();
    kconv_h<<<dim3((SP + BM - 1)/BM, C/BN, NB), 256, SMEM_H>>>();   // 4th launch: ncu slot
    kstats <<<dim3(8, 256), 256>>>();
    kbnp   <<<1, 256>>>(gamma, beta);
    kapply <<<(unsigned)(TOT/4/256), 256>>>(out);
}